// round 11
// baseline (speedup 1.0000x reference)
#include <cuda_runtime.h>
#include <cstdint>

// EvalBspPrimeTF: derivative of Bernstein basis, order 16, 4M points -> [4M,17] f32.
// Telescoping form: U_m = 16*C(15,m)*y^m*(1-y)^(15-m), m=0..15
//   out[0] = -U_0;  out[m] = U_{m-1} - U_m (1<=m<=15);  out[16] = U_15
// Reference NaN->0: at y==0, out[0]=out[1]=0; at y==1, out[15]=out[16]=0.
//
// R11: fully warp-autonomous pipeline — NO block barriers. Each warp stages
// its private 32x17 (2176B) smem chunk, __syncwarp(), and lane 0 issues a
// per-warp TMA bulk store + drains its own group. Stores issue as soon as
// each warp's data is ready instead of waiting for the slowest warp.

#define TPB   128
#define NCOL  17
#define WCHUNK_WORDS (32 * NCOL)          // 544 floats per warp
#define WCHUNK_BYTES (WCHUNK_WORDS * 4)   // 2176 B, multiple of 16

__device__ __forceinline__ void compute_point(float y, float* __restrict__ o)
{
    // 16*C(15,m)
    const float K[16] = {
        16.f, 240.f, 1680.f, 7280.f, 21840.f, 48048.f, 80080.f, 102960.f,
        102960.f, 80080.f, 48048.f, 21840.f, 7280.f, 1680.f, 240.f, 16.f
    };
    float q = 1.0f - y;

    float yp[16], qp[16];
    yp[0] = 1.0f; qp[0] = 1.0f;
#pragma unroll
    for (int k = 1; k < 16; ++k) {
        yp[k] = yp[k - 1] * y;
        qp[k] = qp[k - 1] * q;
    }

    float U[16];
#pragma unroll
    for (int m = 0; m < 16; ++m)
        U[m] = K[m] * yp[m] * qp[15 - m];

    o[0] = -U[0];
#pragma unroll
    for (int m = 1; m < 16; ++m)
        o[m] = U[m - 1] - U[m];
    o[16] = U[15];

    if (y == 0.0f) { o[0]  = 0.0f; o[1]  = 0.0f; }
    if (y == 1.0f) { o[15] = 0.0f; o[16] = 0.0f; }
}

__global__ __launch_bounds__(TPB)
void evalbspprime_kernel(const float* __restrict__ x,
                         float* __restrict__ out,
                         int n)
{
    __shared__ __align__(128) float s[TPB / 32][WCHUNK_WORDS];   // 8704 B

    const int tid  = threadIdx.x;
    const int wid  = tid >> 5;
    const int lane = tid & 31;
    const int base = blockIdx.x * TPB;
    const int idx  = base + tid;

    float y = (idx < n) ? x[idx] : 0.5f;
    float o[NCOL];
    compute_point(y, o);

    // stage this warp's 32x17 chunk; stride 17 coprime to 32 banks
#pragma unroll
    for (int m = 0; m < NCOL; ++m)
        s[wid][lane * NCOL + m] = o[m];

    if (base + TPB <= n) {
        __syncwarp();       // order the warp's smem writes before lane 0's fence
        if (lane == 0) {
            asm volatile("fence.proxy.async.shared::cta;" ::: "memory");
            uint32_t saddr = (uint32_t)__cvta_generic_to_shared(&s[wid][0]);
            const float* g = out + (long long)(base + wid * 32) * NCOL;
            asm volatile(
                "cp.async.bulk.global.shared::cta.bulk_group [%0], [%1], %2;"
                :: "l"(g), "r"(saddr), "n"(WCHUNK_BYTES) : "memory");
            asm volatile("cp.async.bulk.commit_group;" ::: "memory");
            // per-thread group state: each warp drains only its own store
            // before exit (smem dealloc safety). No cross-warp sync needed.
            asm volatile("cp.async.bulk.wait_group.read 0;" ::: "memory");
        }
    } else {
        // tail (absent for n = 4,000,000): block-coalesced scalar fallback
        __syncthreads();
        const long long obase = (long long)base * NCOL;
        const int rem = (n > base) ? (n - base) * NCOL : 0;
        for (int i = tid; i < rem; i += TPB)
            out[obase + i] = s[i / WCHUNK_WORDS][i % WCHUNK_WORDS];
    }
}

extern "C" void kernel_launch(void* const* d_in, const int* in_sizes, int n_in,
                              void* d_out, int out_size)
{
    const float* x = (const float*)d_in[0];
    float* out = (float*)d_out;
    const int n = in_sizes[0];          // 4,000,000
    const int blocks = (n + TPB - 1) / TPB;   // 31250
    evalbspprime_kernel<<<blocks, TPB>>>(x, out, n);
}